// round 10
// baseline (speedup 1.0000x reference)
#include <cuda_runtime.h>
#include <cuda_fp16.h>
#include <math.h>
#include <cstdint>

// Problem constants
#define BB 2
#define TT 2048
#define DD 2048
#define LAT 512
#define PAST 2048
#define S_TOT 4096
#define NH 16
#define HD 128
// (1/sqrt(128)) * log2(e): folded into q epilogue; softmax runs in base-2
#define QSC 0.1275164973623072f

// ---------------------------------------------------------------------------
// Scratch (device globals; no allocations allowed)
// ---------------------------------------------------------------------------
__device__ __half g_x_h[(size_t)BB*TT*DD];
__device__ __half g_latraw_h[(size_t)BB*TT*LAT];
__device__ __half g_lat_h[(size_t)BB*S_TOT*LAT];
__device__ __half g_q_h[(size_t)BB*TT*DD];
__device__ __half g_kv_h[(size_t)BB*S_TOT*2*DD];   // [s, 0:2048]=k, [s, 2048:4096]=v
__device__ __half g_ao_h[(size_t)BB*TT*DD];
__device__ __half g_WqdT[(size_t)(DD+LAT)*DD];     // rows 0..2047: WqT; 2048..2559: WdownT
__device__ __half g_WkvT[(size_t)2*DD*LAT];        // rows 0..2047: WkT; 2048..4095: WvT
__device__ __half g_WoT[(size_t)DD*DD];

// ---------------------------------------------------------------------------
// Base-target PTX helpers (sm_75/80+; no arch-'a' features)
// ---------------------------------------------------------------------------
__device__ __forceinline__ uint32_t smem_to_u32(const void* smem_ptr) {
    uint32_t addr;
    asm("{ .reg .u64 tmp; cvta.to.shared.u64 tmp, %1; cvt.u32.u64 %0, tmp; }"
        : "=r"(addr) : "l"(smem_ptr));
    return addr;
}
__device__ __forceinline__ void cp16(uint32_t dst, const void* src) {
    asm volatile("cp.async.cg.shared.global [%0], [%1], 16;" :: "r"(dst), "l"(src));
}
#define CP_COMMIT() asm volatile("cp.async.commit_group;" ::: "memory")
#define CP_WAIT(n)  asm volatile("cp.async.wait_group %0;" :: "n"(n) : "memory")

__device__ __forceinline__ void ldm_x4(uint32_t r[4], uint32_t addr) {
    asm volatile("ldmatrix.sync.aligned.m8n8.x4.shared.b16 {%0,%1,%2,%3}, [%4];"
        : "=r"(r[0]), "=r"(r[1]), "=r"(r[2]), "=r"(r[3]) : "r"(addr));
}
__device__ __forceinline__ void ldm_x4_trans(uint32_t r[4], uint32_t addr) {
    asm volatile("ldmatrix.sync.aligned.m8n8.x4.trans.shared.b16 {%0,%1,%2,%3}, [%4];"
        : "=r"(r[0]), "=r"(r[1]), "=r"(r[2]), "=r"(r[3]) : "r"(addr));
}

// m16n8k16 row.col fp16 in, fp32 accum
__device__ __forceinline__ void mma16816(float d[4], const uint32_t a[4], const uint32_t b[2]) {
    asm volatile(
        "mma.sync.aligned.m16n8k16.row.col.f32.f16.f16.f32 "
        "{%0,%1,%2,%3}, {%4,%5,%6,%7}, {%8,%9}, {%0,%1,%2,%3};"
        : "+f"(d[0]), "+f"(d[1]), "+f"(d[2]), "+f"(d[3])
        : "r"(a[0]), "r"(a[1]), "r"(a[2]), "r"(a[3]), "r"(b[0]), "r"(b[1]));
}

// ---------------------------------------------------------------------------
// Fused prep kernel: x->fp16, latent_prev copy, all 5 weight transposes.
// ---------------------------------------------------------------------------
__device__ __forceinline__ void transpose_block(
    const float* __restrict__ W, __half* __restrict__ Wt,
    int K, int N, int n0, int k0, int tid, float* t /*[32*33]*/)
{
    const int x = tid & 31, y = tid >> 5;
#pragma unroll
    for (int i = 0; i < 32; i += 8)
        t[(y + i) * 33 + x] = W[(size_t)(k0 + y + i) * N + n0 + x];
    __syncthreads();
#pragma unroll
    for (int i = 0; i < 32; i += 8)
        Wt[(size_t)(n0 + y + i) * K + k0 + x] = __float2half(t[x * 33 + y + i]);
}

__global__ void __launch_bounds__(256) prep_kernel(
    const float* __restrict__ x, const float* __restrict__ lprev,
    const float* __restrict__ Wq, const float* __restrict__ Wdown,
    const float* __restrict__ Wk, const float* __restrict__ Wv,
    const float* __restrict__ Wo,
    __half* __restrict__ x_h, __half* __restrict__ lat_h,
    __half* __restrict__ WqdT, __half* __restrict__ WkvT, __half* __restrict__ WoT)
{
    __shared__ float t[32 * 33];
    const int blk = blockIdx.x;
    const int tid = threadIdx.x;

    if (blk < 8192) {                       // x -> fp16
        size_t i = (size_t)blk * 256 + tid;
        float4 v = ((const float4*)x)[i];
        __half2* o = (__half2*)x_h + 2 * i;
        o[0] = __floats2half2_rn(v.x, v.y);
        o[1] = __floats2half2_rn(v.z, v.w);
    } else if (blk < 10240) {               // latent_prev -> fp16 into lat_h[:, :PAST]
        size_t i = (size_t)(blk - 8192) * 256 + tid;
        const size_t per_b = (size_t)PAST * LAT / 4;
        size_t b = i / per_b, r = i % per_b;
        float4 v = ((const float4*)lprev)[i];
        __half2* d = (__half2*)(lat_h + b * (size_t)S_TOT * LAT) + r * 2;
        d[0] = __floats2half2_rn(v.x, v.y);
        d[1] = __floats2half2_rn(v.z, v.w);
    } else if (blk < 14336) {               // Wq^T
        int local = blk - 10240;
        transpose_block(Wq, WqdT, DD, DD, (local & 63) * 32, (local >> 6) * 32, tid, t);
    } else if (blk < 15360) {               // Wdown^T
        int local = blk - 14336;
        transpose_block(Wdown, WqdT + (size_t)DD * DD, DD, LAT,
                        (local & 15) * 32, (local >> 4) * 32, tid, t);
    } else if (blk < 16384) {               // Wk^T
        int local = blk - 15360;
        transpose_block(Wk, WkvT, LAT, DD, (local & 63) * 32, (local >> 6) * 32, tid, t);
    } else if (blk < 17408) {               // Wv^T
        int local = blk - 16384;
        transpose_block(Wv, WkvT + (size_t)DD * LAT, LAT, DD,
                        (local & 63) * 32, (local >> 6) * 32, tid, t);
    } else {                                // Wo^T
        int local = blk - 17408;
        transpose_block(Wo, WoT, DD, DD, (local & 63) * 32, (local >> 6) * 32, tid, t);
    }
}

// ---------------------------------------------------------------------------
// LayerNorm over LAT=512 (fp16 input) -> fp16 latent
// ---------------------------------------------------------------------------
__global__ void __launch_bounds__(128) ln_kernel(
    const __half* __restrict__ raw, const float* __restrict__ g,
    const float* __restrict__ bvec, __half* __restrict__ latent)
{
    const int row = blockIdx.x;
    const int b = row / TT, t = row % TT;
    const int tid = threadIdx.x;

    const __half2* xr = (const __half2*)(raw + (size_t)row * LAT) + tid * 2;
    float2 x01 = __half22float2(xr[0]);
    float2 x23 = __half22float2(xr[1]);
    float4 xv = make_float4(x01.x, x01.y, x23.x, x23.y);
    float s = xv.x + xv.y + xv.z + xv.w;
    float s2 = xv.x * xv.x + xv.y * xv.y + xv.z * xv.z + xv.w * xv.w;

    __shared__ float red[8];
#pragma unroll
    for (int off = 16; off; off >>= 1) {
        s  += __shfl_xor_sync(0xffffffffu, s,  off);
        s2 += __shfl_xor_sync(0xffffffffu, s2, off);
    }
    const int wid = tid >> 5, lane = tid & 31;
    if (lane == 0) { red[wid] = s; red[4 + wid] = s2; }
    __syncthreads();
    s  = red[0] + red[1] + red[2] + red[3];
    s2 = red[4] + red[5] + red[6] + red[7];

    const float mean = s * (1.f / LAT);
    const float var = s2 * (1.f / LAT) - mean * mean;
    const float rs = rsqrtf(var + 1e-5f);

    float4 gv = *(const float4*)(g + tid * 4);
    float4 bv = *(const float4*)(bvec + tid * 4);
    __half2* yr = (__half2*)(latent + ((size_t)b * S_TOT + PAST + t) * LAT) + tid * 2;
    yr[0] = __floats2half2_rn((xv.x - mean) * rs * gv.x + bv.x,
                              (xv.y - mean) * rs * gv.y + bv.y);
    yr[1] = __floats2half2_rn((xv.z - mean) * rs * gv.z + bv.z,
                              (xv.w - mean) * rs * gv.w + bv.w);
}

// ---------------------------------------------------------------------------
// HGEMM (mma.sync + ldmatrix): C[M,N] = A[M,K] @ Bt[N,K]^T
// 128x128 tile, 8 warps (2x4), warp tile 64x32.
// Ktile=64 (R10: halves per-tile sync/wait bubbles), row stride 72 halves
// (144B: conflict-free ldmatrix — 144 mod 128 walks all eight 16B banks).
// 3-stage cp.async (110.6 KB/CTA; 2 CTAs = 221 KB < 228 KB).
// __launch_bounds__(256, 2): 2 CTAs/SM.
// EPI 0: fp32 out. EPI 1: fp16 out (scaled). EPI 2: split output.
// ---------------------------------------------------------------------------
#define GROW 72
#define GTB  (128 * GROW * 2)        // 18432 bytes per matrix per stage
#define GST  (2 * GTB)               // 36864 bytes per stage
template<int EPI>
__global__ void __launch_bounds__(256, 2) hgemm(
    const __half* __restrict__ A, const __half* __restrict__ Bt,
    float* __restrict__ Cf, __half* __restrict__ Ch, __half* __restrict__ Ch2,
    int M, int N, int K, int Ns, float oscale)
{
    extern __shared__ __half smh[];
    const uint32_t su = smem_to_u32(smh);
    const int tid = threadIdx.x;
    const int lane = tid & 31, wid = tid >> 5;
    const int wm = wid >> 2, wn = wid & 3;
    const int m0 = blockIdx.y * 128, n0 = blockIdx.x * 128;
    const int r = lane >> 2, cc = (lane & 3) * 2;
    const int laddA = lane & 15;
    const int lcolA = (lane >> 4) << 3;
    const int laddB = (lane & 7) | ((lane & 16) >> 1);
    const int lcolB = lane & 8;

    // cp.async mapping: 2 threads per row, 64B (4x cp16) each per matrix
    const int lrow = tid >> 1, halfsel = tid & 1;
    const __half* Abase = A + (size_t)(m0 + lrow) * K + halfsel * 32;
    const __half* Bbase = Bt + (size_t)(n0 + lrow) * K + halfsel * 32;
    const uint32_t dA = su + lrow * 144 + halfsel * 64;
    const uint32_t dB = dA + GTB;

    float acc[4][4][4];
#pragma unroll
    for (int i = 0; i < 4; i++)
#pragma unroll
        for (int j = 0; j < 4; j++)
#pragma unroll
            for (int q = 0; q < 4; q++) acc[i][j][q] = 0.f;

    const int niter = K >> 6;   // Ktile = 64
    auto issue = [&](int kt, int st) {
        const __half* ga = Abase + kt * 64;
        const __half* gb = Bbase + kt * 64;
#pragma unroll
        for (int u = 0; u < 4; u++) {
            cp16(dA + st * GST + u * 16, ga + u * 8);
            cp16(dB + st * GST + u * 16, gb + u * 8);
        }
    };
    issue(0, 0); CP_COMMIT();
    issue(1, 1); CP_COMMIT();

    int cons = 0;   // stage being consumed
    int prod = 2;   // stage to fill next
    for (int kt = 0; kt < niter; kt++) {
        CP_WAIT(1);
        __syncthreads();
        if (kt + 2 < niter) issue(kt + 2, prod);
        CP_COMMIT();
        const uint32_t asu = su + cons * GST;
        const uint32_t bsu = asu + GTB;
#pragma unroll
        for (int k0 = 0; k0 < 64; k0 += 16) {
            uint32_t a[4][4], b[4][2];
#pragma unroll
            for (int i = 0; i < 4; i++)
                ldm_x4(a[i], asu + ((wm * 64 + 16 * i + laddA) * GROW + k0 + lcolA) * 2);
#pragma unroll
            for (int jp = 0; jp < 2; jp++) {
                uint32_t t4[4];
                ldm_x4(t4, bsu + ((wn * 32 + 16 * jp + laddB) * GROW + k0 + lcolB) * 2);
                b[2 * jp][0] = t4[0];   b[2 * jp][1] = t4[1];
                b[2 * jp + 1][0] = t4[2]; b[2 * jp + 1][1] = t4[3];
            }
#pragma unroll
            for (int i = 0; i < 4; i++)
#pragma unroll
                for (int j = 0; j < 4; j++)
                    mma16816(acc[i][j], a[i], b[j]);
        }
        cons = (cons == 2) ? 0 : cons + 1;
        prod = (prod == 2) ? 0 : prod + 1;
    }

#pragma unroll
    for (int i = 0; i < 4; i++) {
        const int gr0 = m0 + wm * 64 + 16 * i + r;
        const int gr1 = gr0 + 8;
#pragma unroll
        for (int j = 0; j < 4; j++) {
            const int gc = n0 + wn * 32 + 8 * j + cc;
            const float* ac = acc[i][j];
            if (EPI == 0) {
                *(float2*)&Cf[(size_t)gr0 * N + gc] = make_float2(ac[0], ac[1]);
                *(float2*)&Cf[(size_t)gr1 * N + gc] = make_float2(ac[2], ac[3]);
            } else if (EPI == 1) {
                __half2 h0 = __floats2half2_rn(ac[0] * oscale, ac[1] * oscale);
                __half2 h1 = __floats2half2_rn(ac[2] * oscale, ac[3] * oscale);
                *(__half2*)&Ch[(size_t)gr0 * N + gc] = h0;
                *(__half2*)&Ch[(size_t)gr1 * N + gc] = h1;
            } else {  // EPI == 2: split output (uniform branch per CTA)
                if (n0 < Ns) {
                    __half2 h0 = __floats2half2_rn(ac[0] * oscale, ac[1] * oscale);
                    __half2 h1 = __floats2half2_rn(ac[2] * oscale, ac[3] * oscale);
                    *(__half2*)&Ch[(size_t)gr0 * Ns + gc] = h0;
                    *(__half2*)&Ch[(size_t)gr1 * Ns + gc] = h1;
                } else {
                    const int N2 = N - Ns, gc2 = gc - Ns;
                    __half2 h0 = __floats2half2_rn(ac[0], ac[1]);
                    __half2 h1 = __floats2half2_rn(ac[2], ac[3]);
                    *(__half2*)&Ch2[(size_t)gr0 * N2 + gc2] = h0;
                    *(__half2*)&Ch2[(size_t)gr1 * N2 + gc2] = h1;
                }
            }
        }
    }
}

// ---------------------------------------------------------------------------
// Flash attention (mma.sync + ldmatrix), static-offset base-2 softmax.
// Split-S: each 64-chunk processed as two 32-wide groups (QK -> softmax -> PV)
// to halve sacc/pa live ranges -> spill-free at the 128-reg / 2-CTA cap.
// smem: Q[128][136] | K[2][64][136] | V[2][64][136]
// ---------------------------------------------------------------------------
#define FSM_BYTES 104448
#define KVW (2 * DD)
__global__ void __launch_bounds__(256, 2) flash_h(
    const __half* __restrict__ Qg, const __half* __restrict__ KVg,
    __half* __restrict__ Og)
{
    extern __shared__ __half smh[];
    const uint32_t su = smem_to_u32(smh);
    const int tid = threadIdx.x, lane = tid & 31, wid = tid >> 5;

    // LPT decode: linear bid L -> (mtile descending in L, h, b)
    const int L = blockIdx.x + 16 * blockIdx.y + 256 * blockIdx.z;
    const int mt = 15 - (L >> 5);
    const int h = L & 15;
    const int b = (L >> 4) & 1;
    const int m0 = mt * 128;

    const int r = lane >> 2, cc = (lane & 3) * 2;
    const int laddA = lane & 15;
    const int lcolA = (lane >> 4) << 3;
    const int laddB = (lane & 7) | ((lane & 16) >> 1);
    const int lcolB = lane & 8;

    // Issue Q tile (128 rows x 256B)
#pragma unroll
    for (int u = 0; u < 8; u++) {
        int c = u * 256 + tid;
        int row = c >> 4, seg = c & 15;
        const __half* src = Qg + (size_t)(b * TT + m0 + row) * DD + h * HD + seg * 8;
        cp16(su + row * 272 + seg * 16, src);
    }
    CP_COMMIT();

    auto issueKV = [&](int it) {
        const int st = it & 1;
        const int s0 = it * 64;
        const __half* base = KVg + (size_t)(b * S_TOT + s0) * KVW + h * HD;
#pragma unroll
        for (int u = 0; u < 4; u++) {
            int c = u * 256 + tid;
            int row = c >> 4, seg = c & 15;
            cp16(su + 34816 + st * 17408 + row * 272 + seg * 16,
                 base + (size_t)row * KVW + seg * 8);
        }
#pragma unroll
        for (int u = 0; u < 4; u++) {
            int c = u * 256 + tid;
            int row = c >> 4, seg = c & 15;
            cp16(su + 69632 + st * 17408 + row * 272 + seg * 16,
                 base + (size_t)row * KVW + DD + seg * 8);
        }
    };
    issueKV(0); CP_COMMIT();

    CP_WAIT(1);
    __syncthreads();

    float oacc[16][4];
#pragma unroll
    for (int nn = 0; nn < 16; nn++)
#pragma unroll
        for (int q = 0; q < 4; q++) oacc[nn][q] = 0.f;
    float li[2] = {0.f, 0.f};
    const int trow0 = m0 + wid * 16 + r;
    const uint32_t qbase = su + ((wid * 16 + laddA) * 136 + lcolA) * 2;

    const int nchunks = 34 + 2 * mt;
    for (int it = 0; it < nchunks; it++) {
        CP_WAIT(0);
        __syncthreads();
        if (it + 1 < nchunks) issueKV(it + 1);
        CP_COMMIT();
        const int st = it & 1;
        const uint32_t ksb = su + 34816 + st * 17408;
        const uint32_t vsb = su + 69632 + st * 17408;
        const int n0s = it * 64;

#pragma unroll
        for (int jg = 0; jg < 2; jg++) {
            // S = Q K^T for 32 columns (fp32 accum); Q frags reloaded per kk
            float sacc[4][4];
#pragma unroll
            for (int j = 0; j < 4; j++)
#pragma unroll
                for (int q = 0; q < 4; q++) sacc[j][q] = 0.f;
#pragma unroll
            for (int kk = 0; kk < 8; kk++) {
                uint32_t qf[4];
                ldm_x4(qf, qbase + kk * 32);
                uint32_t kb[4][2];
#pragma unroll
                for (int jp = 0; jp < 2; jp++) {
                    uint32_t t4[4];
                    ldm_x4(t4, ksb + ((jg * 32 + 16 * jp + laddB) * 136 + kk * 16 + lcolB) * 2);
                    kb[2 * jp][0] = t4[0];   kb[2 * jp][1] = t4[1];
                    kb[2 * jp + 1][0] = t4[2]; kb[2 * jp + 1][1] = t4[3];
                }
#pragma unroll
                for (int j = 0; j < 4; j++)
                    mma16816(sacc[j], qf, kb[j]);
            }

            // p = 2^s via ex2.f16x2 (static-offset base-2 softmax)
            uint32_t pa[2][4];
#pragma unroll
            for (int hh = 0; hh < 2; hh++) {
                const int trow = trow0 + 8 * hh;
                const int vislim = PAST + trow - n0s;   // inclusive local col limit
                __half2 hs = __floats2half2_rn(0.f, 0.f);
#pragma unroll
                for (int j = 0; j < 4; j++) {
                    float v0 = sacc[j][2 * hh];
                    float v1 = sacc[j][2 * hh + 1];
                    if (vislim < 63) {
                        const int gcol = jg * 32 + 8 * j + cc;
                        if (gcol     > vislim) v0 = -1e30f;
                        if (gcol + 1 > vislim) v1 = -1e30f;
                    }
                    __half2 hl = __floats2half2_rn(v0, v1);
                    __half2 pe = h2exp2(hl);
                    pa[hh][j] = *(uint32_t*)&pe;
                    hs = __hadd2(hs, pe);
                }
                float2 fs = __half22float2(hs);
                li[hh] += fs.x + fs.y;
            }

            // O += P @ V for these 32 s-positions (V B-frags via ldmatrix.trans)
#pragma unroll
            for (int k2l = 0; k2l < 2; k2l++) {
                const int k2 = jg * 2 + k2l;
                uint32_t ap[4] = { pa[0][2 * k2l], pa[1][2 * k2l],
                                   pa[0][2 * k2l + 1], pa[1][2 * k2l + 1] };
#pragma unroll
                for (int np = 0; np < 8; np++) {
                    uint32_t t4[4];
                    ldm_x4_trans(t4, vsb + ((k2 * 16 + laddA) * 136 + np * 16 + lcolA) * 2);
                    mma16816(oacc[2 * np],     ap, &t4[0]);
                    mma16816(oacc[2 * np + 1], ap, &t4[2]);
                }
            }
        }
    }

    // Reduce li across the quad, normalize, store
#pragma unroll
    for (int hh = 0; hh < 2; hh++) {
        li[hh] += __shfl_xor_sync(0xffffffffu, li[hh], 1);
        li[hh] += __shfl_xor_sync(0xffffffffu, li[hh], 2);
    }
    const float inv0 = 1.f / li[0], inv1 = 1.f / li[1];
#pragma unroll
    for (int nn = 0; nn < 16; nn++) {
        __half2 h0 = __floats2half2_rn(oacc[nn][0] * inv0, oacc[nn][1] * inv0);
        __half2 h1 = __floats2half2_rn(oacc[nn][2] * inv1, oacc[nn][3] * inv1);
        *(__half2*)&Og[(size_t)(b * TT + trow0) * DD + h * HD + nn * 8 + cc] = h0;
        *(__half2*)&Og[(size_t)(b * TT + trow0 + 8) * DD + h * HD + nn * 8 + cc] = h1;
    }
}

// ---------------------------------------------------------------------------
extern "C" void kernel_launch(void* const* d_in, const int* in_sizes, int n_in,
                              void* d_out, int out_size)
{
    (void)in_sizes; (void)n_in; (void)out_size;
    const float* x     = (const float*)d_in[0];
    const float* lprev = (const float*)d_in[1];
    const float* Wq    = (const float*)d_in[2];
    const float* Wdown = (const float*)d_in[3];
    const float* Wk_up = (const float*)d_in[4];
    const float* Wv_up = (const float*)d_in[5];
    const float* ln_g  = (const float*)d_in[6];
    const float* ln_b  = (const float*)d_in[7];
    const float* Wo    = (const float*)d_in[8];
    float* out = (float*)d_out;

    __half *x_h, *latraw_h, *lat_h, *q_h, *kv_h, *ao_h, *WqdT, *WkvT, *WoT;
    cudaGetSymbolAddress((void**)&x_h,      g_x_h);
    cudaGetSymbolAddress((void**)&latraw_h, g_latraw_h);
    cudaGetSymbolAddress((void**)&lat_h,    g_lat_h);
    cudaGetSymbolAddress((void**)&q_h,      g_q_h);
    cudaGetSymbolAddress((void**)&kv_h,     g_kv_h);
    cudaGetSymbolAddress((void**)&ao_h,     g_ao_h);
    cudaGetSymbolAddress((void**)&WqdT,     g_WqdT);
    cudaGetSymbolAddress((void**)&WkvT,     g_WkvT);
    cudaGetSymbolAddress((void**)&WoT,      g_WoT);

    cudaFuncSetAttribute(hgemm<0>, cudaFuncAttributeMaxDynamicSharedMemorySize, 3 * GST);
    cudaFuncSetAttribute(hgemm<1>, cudaFuncAttributeMaxDynamicSharedMemorySize, 3 * GST);
    cudaFuncSetAttribute(hgemm<2>, cudaFuncAttributeMaxDynamicSharedMemorySize, 3 * GST);
    cudaFuncSetAttribute(flash_h, cudaFuncAttributeMaxDynamicSharedMemorySize, FSM_BYTES);

    // 0: fused prep (x->fp16, prev-copy, 5 transposes)
    prep_kernel<<<21504, 256>>>(x, lprev, Wq, Wdown, Wk_up, Wv_up, Wo,
                                x_h, lat_h, WqdT, WkvT, WoT);
    // 1: [q | latraw] = x @ [Wq | Wdown]  (N=2560 split epilogue)
    hgemm<2><<<dim3((DD+LAT)/128, BB*TT/128), 256, 3*GST>>>(
        x_h, WqdT, nullptr, q_h, latraw_h, BB*TT, DD+LAT, DD, DD, QSC);
    // 2: latent[:, PAST:] = LN(latraw)
    ln_kernel<<<BB*TT, 128>>>(latraw_h, ln_g, ln_b, lat_h);
    // 3: [k | v] = latent @ [Wk | Wv]  (fused KV)  [PROFILED SLOT - index 3]
    hgemm<1><<<dim3(2*DD/128, BB*S_TOT/128), 256, 3*GST>>>(
        lat_h, WkvT, nullptr, kv_h, nullptr, BB*S_TOT, 2*DD, LAT, 0, 1.f);
    // 4: flash attention -> ao
    flash_h<<<dim3(16, 16, 2), 256, FSM_BYTES>>>(q_h, kv_h, ao_h);
    // 5: out = ao @ Wo (fp32)
    hgemm<0><<<dim3(DD/128, BB*TT/128), 256, 3*GST>>>(
        ao_h, WoT, out, nullptr, nullptr, BB*TT, DD, DD, 0, 1.f);
}

// round 11
// speedup vs baseline: 1.0952x; 1.0952x over previous
#include <cuda_runtime.h>
#include <cuda_fp16.h>
#include <math.h>
#include <cstdint>

// Problem constants
#define BB 2
#define TT 2048
#define DD 2048
#define LAT 512
#define PAST 2048
#define S_TOT 4096
#define NH 16
#define HD 128
// (1/sqrt(128)) * log2(e): folded into q epilogue; softmax runs in base-2
#define QSC 0.1275164973623072f

// ---------------------------------------------------------------------------
// Scratch (device globals; no allocations allowed)
// ---------------------------------------------------------------------------
__device__ __half g_x_h[(size_t)BB*TT*DD];
__device__ __half g_latraw_h[(size_t)BB*TT*LAT];
__device__ __half g_lat_h[(size_t)BB*S_TOT*LAT];
__device__ __half g_q_h[(size_t)BB*TT*DD];
__device__ __half g_kv_h[(size_t)BB*S_TOT*2*DD];   // [s, 0:2048]=k, [s, 2048:4096]=v
__device__ __half g_ao_h[(size_t)BB*TT*DD];
__device__ __half g_WqdT[(size_t)(DD+LAT)*DD];     // rows 0..2047: WqT; 2048..2559: WdownT
__device__ __half g_WkvT[(size_t)2*DD*LAT];        // rows 0..2047: WkT; 2048..4095: WvT
__device__ __half g_WoT[(size_t)DD*DD];

// ---------------------------------------------------------------------------
// Base-target PTX helpers (sm_75/80+; no arch-'a' features)
// ---------------------------------------------------------------------------
__device__ __forceinline__ uint32_t smem_to_u32(const void* smem_ptr) {
    uint32_t addr;
    asm("{ .reg .u64 tmp; cvta.to.shared.u64 tmp, %1; cvt.u32.u64 %0, tmp; }"
        : "=r"(addr) : "l"(smem_ptr));
    return addr;
}
__device__ __forceinline__ void cp16(uint32_t dst, const void* src) {
    asm volatile("cp.async.cg.shared.global [%0], [%1], 16;" :: "r"(dst), "l"(src));
}
#define CP_COMMIT() asm volatile("cp.async.commit_group;" ::: "memory")
#define CP_WAIT(n)  asm volatile("cp.async.wait_group %0;" :: "n"(n) : "memory")

__device__ __forceinline__ void ldm_x4(uint32_t r[4], uint32_t addr) {
    asm volatile("ldmatrix.sync.aligned.m8n8.x4.shared.b16 {%0,%1,%2,%3}, [%4];"
        : "=r"(r[0]), "=r"(r[1]), "=r"(r[2]), "=r"(r[3]) : "r"(addr));
}
__device__ __forceinline__ void ldm_x4_trans(uint32_t r[4], uint32_t addr) {
    asm volatile("ldmatrix.sync.aligned.m8n8.x4.trans.shared.b16 {%0,%1,%2,%3}, [%4];"
        : "=r"(r[0]), "=r"(r[1]), "=r"(r[2]), "=r"(r[3]) : "r"(addr));
}

// m16n8k16 row.col fp16 in, fp32 accum
__device__ __forceinline__ void mma16816(float d[4], const uint32_t a[4], const uint32_t b[2]) {
    asm volatile(
        "mma.sync.aligned.m16n8k16.row.col.f32.f16.f16.f32 "
        "{%0,%1,%2,%3}, {%4,%5,%6,%7}, {%8,%9}, {%0,%1,%2,%3};"
        : "+f"(d[0]), "+f"(d[1]), "+f"(d[2]), "+f"(d[3])
        : "r"(a[0]), "r"(a[1]), "r"(a[2]), "r"(a[3]), "r"(b[0]), "r"(b[1]));
}

// ---------------------------------------------------------------------------
// Fused prep kernel: x->fp16, latent_prev copy, all 5 weight transposes.
// ---------------------------------------------------------------------------
__device__ __forceinline__ void transpose_block(
    const float* __restrict__ W, __half* __restrict__ Wt,
    int K, int N, int n0, int k0, int tid, float* t /*[32*33]*/)
{
    const int x = tid & 31, y = tid >> 5;
#pragma unroll
    for (int i = 0; i < 32; i += 8)
        t[(y + i) * 33 + x] = W[(size_t)(k0 + y + i) * N + n0 + x];
    __syncthreads();
#pragma unroll
    for (int i = 0; i < 32; i += 8)
        Wt[(size_t)(n0 + y + i) * K + k0 + x] = __float2half(t[x * 33 + y + i]);
}

__global__ void __launch_bounds__(256) prep_kernel(
    const float* __restrict__ x, const float* __restrict__ lprev,
    const float* __restrict__ Wq, const float* __restrict__ Wdown,
    const float* __restrict__ Wk, const float* __restrict__ Wv,
    const float* __restrict__ Wo,
    __half* __restrict__ x_h, __half* __restrict__ lat_h,
    __half* __restrict__ WqdT, __half* __restrict__ WkvT, __half* __restrict__ WoT)
{
    __shared__ float t[32 * 33];
    const int blk = blockIdx.x;
    const int tid = threadIdx.x;

    if (blk < 8192) {                       // x -> fp16
        size_t i = (size_t)blk * 256 + tid;
        float4 v = ((const float4*)x)[i];
        __half2* o = (__half2*)x_h + 2 * i;
        o[0] = __floats2half2_rn(v.x, v.y);
        o[1] = __floats2half2_rn(v.z, v.w);
    } else if (blk < 10240) {               // latent_prev -> fp16 into lat_h[:, :PAST]
        size_t i = (size_t)(blk - 8192) * 256 + tid;
        const size_t per_b = (size_t)PAST * LAT / 4;
        size_t b = i / per_b, r = i % per_b;
        float4 v = ((const float4*)lprev)[i];
        __half2* d = (__half2*)(lat_h + b * (size_t)S_TOT * LAT) + r * 2;
        d[0] = __floats2half2_rn(v.x, v.y);
        d[1] = __floats2half2_rn(v.z, v.w);
    } else if (blk < 14336) {               // Wq^T
        int local = blk - 10240;
        transpose_block(Wq, WqdT, DD, DD, (local & 63) * 32, (local >> 6) * 32, tid, t);
    } else if (blk < 15360) {               // Wdown^T
        int local = blk - 14336;
        transpose_block(Wdown, WqdT + (size_t)DD * DD, DD, LAT,
                        (local & 15) * 32, (local >> 4) * 32, tid, t);
    } else if (blk < 16384) {               // Wk^T
        int local = blk - 15360;
        transpose_block(Wk, WkvT, LAT, DD, (local & 63) * 32, (local >> 6) * 32, tid, t);
    } else if (blk < 17408) {               // Wv^T
        int local = blk - 16384;
        transpose_block(Wv, WkvT + (size_t)DD * LAT, LAT, DD,
                        (local & 63) * 32, (local >> 6) * 32, tid, t);
    } else {                                // Wo^T
        int local = blk - 17408;
        transpose_block(Wo, WoT, DD, DD, (local & 63) * 32, (local >> 6) * 32, tid, t);
    }
}

// ---------------------------------------------------------------------------
// LayerNorm over LAT=512 (fp16 input) -> fp16 latent
// ---------------------------------------------------------------------------
__global__ void __launch_bounds__(128) ln_kernel(
    const __half* __restrict__ raw, const float* __restrict__ g,
    const float* __restrict__ bvec, __half* __restrict__ latent)
{
    const int row = blockIdx.x;
    const int b = row / TT, t = row % TT;
    const int tid = threadIdx.x;

    const __half2* xr = (const __half2*)(raw + (size_t)row * LAT) + tid * 2;
    float2 x01 = __half22float2(xr[0]);
    float2 x23 = __half22float2(xr[1]);
    float4 xv = make_float4(x01.x, x01.y, x23.x, x23.y);
    float s = xv.x + xv.y + xv.z + xv.w;
    float s2 = xv.x * xv.x + xv.y * xv.y + xv.z * xv.z + xv.w * xv.w;

    __shared__ float red[8];
#pragma unroll
    for (int off = 16; off; off >>= 1) {
        s  += __shfl_xor_sync(0xffffffffu, s,  off);
        s2 += __shfl_xor_sync(0xffffffffu, s2, off);
    }
    const int wid = tid >> 5, lane = tid & 31;
    if (lane == 0) { red[wid] = s; red[4 + wid] = s2; }
    __syncthreads();
    s  = red[0] + red[1] + red[2] + red[3];
    s2 = red[4] + red[5] + red[6] + red[7];

    const float mean = s * (1.f / LAT);
    const float var = s2 * (1.f / LAT) - mean * mean;
    const float rs = rsqrtf(var + 1e-5f);

    float4 gv = *(const float4*)(g + tid * 4);
    float4 bv = *(const float4*)(bvec + tid * 4);
    __half2* yr = (__half2*)(latent + ((size_t)b * S_TOT + PAST + t) * LAT) + tid * 2;
    yr[0] = __floats2half2_rn((xv.x - mean) * rs * gv.x + bv.x,
                              (xv.y - mean) * rs * gv.y + bv.y);
    yr[1] = __floats2half2_rn((xv.z - mean) * rs * gv.z + bv.z,
                              (xv.w - mean) * rs * gv.w + bv.w);
}

// ---------------------------------------------------------------------------
// HGEMM (mma.sync + ldmatrix): C[M,N] = A[M,K] @ Bt[N,K]^T
// R9 configuration restored EXACTLY (R10's Ktile=64/3-stage regressed:
// coarser cp.async waits hide L2 latency worse than 4 finer stages).
// 128x128 tile, 8 warps (2x4), warp tile 64x32, Ktile=32, 4-stage cp.async.
// __launch_bounds__(256, 2): 2 CTAs/SM.
// EPI 0: fp32 out. EPI 1: fp16 out (scaled). EPI 2: split output.
// ---------------------------------------------------------------------------
#define GST 20480
template<int EPI>
__global__ void __launch_bounds__(256, 2) hgemm(
    const __half* __restrict__ A, const __half* __restrict__ Bt,
    float* __restrict__ Cf, __half* __restrict__ Ch, __half* __restrict__ Ch2,
    int M, int N, int K, int Ns, float oscale)
{
    extern __shared__ __half smh[];
    const uint32_t su = smem_to_u32(smh);
    const int tid = threadIdx.x;
    const int lane = tid & 31, wid = tid >> 5;
    const int wm = wid >> 2, wn = wid & 3;
    const int m0 = blockIdx.y * 128, n0 = blockIdx.x * 128;
    const int r = lane >> 2, cc = (lane & 3) * 2;
    const int laddA = lane & 15;
    const int lcolA = (lane >> 4) << 3;
    const int laddB = (lane & 7) | ((lane & 16) >> 1);
    const int lcolB = lane & 8;

    const int lrow = tid >> 1, sb2 = (tid & 1) * 2;
    const __half* Abase = A + (size_t)(m0 + lrow) * K + sb2 * 8;
    const __half* Bbase = Bt + (size_t)(n0 + lrow) * K + sb2 * 8;
    const uint32_t dA = su + lrow * 80 + sb2 * 16;
    const uint32_t dB = dA + 10240;

    float acc[4][4][4];
#pragma unroll
    for (int i = 0; i < 4; i++)
#pragma unroll
        for (int j = 0; j < 4; j++)
#pragma unroll
            for (int q = 0; q < 4; q++) acc[i][j][q] = 0.f;

    const int niter = K >> 5;
    auto issue = [&](int kt) {
        const int st = kt & 3;
        const __half* ga = Abase + kt * 32;
        const __half* gb = Bbase + kt * 32;
        cp16(dA + st * GST, ga);       cp16(dA + st * GST + 16, ga + 8);
        cp16(dB + st * GST, gb);       cp16(dB + st * GST + 16, gb + 8);
    };
    issue(0); CP_COMMIT();
    issue(1); CP_COMMIT();
    issue(2); CP_COMMIT();

    for (int kt = 0; kt < niter; kt++) {
        CP_WAIT(2);
        __syncthreads();
        if (kt + 3 < niter) issue(kt + 3);
        CP_COMMIT();
        const int st = kt & 3;
        const uint32_t asu = su + st * GST;
        const uint32_t bsu = asu + 10240;
#pragma unroll
        for (int k0 = 0; k0 < 32; k0 += 16) {
            uint32_t a[4][4], b[4][2];
#pragma unroll
            for (int i = 0; i < 4; i++)
                ldm_x4(a[i], asu + ((wm * 64 + 16 * i + laddA) * 40 + k0 + lcolA) * 2);
#pragma unroll
            for (int jp = 0; jp < 2; jp++) {
                uint32_t t4[4];
                ldm_x4(t4, bsu + ((wn * 32 + 16 * jp + laddB) * 40 + k0 + lcolB) * 2);
                b[2 * jp][0] = t4[0];   b[2 * jp][1] = t4[1];
                b[2 * jp + 1][0] = t4[2]; b[2 * jp + 1][1] = t4[3];
            }
#pragma unroll
            for (int i = 0; i < 4; i++)
#pragma unroll
                for (int j = 0; j < 4; j++)
                    mma16816(acc[i][j], a[i], b[j]);
        }
    }

#pragma unroll
    for (int i = 0; i < 4; i++) {
        const int gr0 = m0 + wm * 64 + 16 * i + r;
        const int gr1 = gr0 + 8;
#pragma unroll
        for (int j = 0; j < 4; j++) {
            const int gc = n0 + wn * 32 + 8 * j + cc;
            const float* ac = acc[i][j];
            if (EPI == 0) {
                *(float2*)&Cf[(size_t)gr0 * N + gc] = make_float2(ac[0], ac[1]);
                *(float2*)&Cf[(size_t)gr1 * N + gc] = make_float2(ac[2], ac[3]);
            } else if (EPI == 1) {
                __half2 h0 = __floats2half2_rn(ac[0] * oscale, ac[1] * oscale);
                __half2 h1 = __floats2half2_rn(ac[2] * oscale, ac[3] * oscale);
                *(__half2*)&Ch[(size_t)gr0 * N + gc] = h0;
                *(__half2*)&Ch[(size_t)gr1 * N + gc] = h1;
            } else {  // EPI == 2: split output (uniform branch per CTA)
                if (n0 < Ns) {
                    __half2 h0 = __floats2half2_rn(ac[0] * oscale, ac[1] * oscale);
                    __half2 h1 = __floats2half2_rn(ac[2] * oscale, ac[3] * oscale);
                    *(__half2*)&Ch[(size_t)gr0 * Ns + gc] = h0;
                    *(__half2*)&Ch[(size_t)gr1 * Ns + gc] = h1;
                } else {
                    const int N2 = N - Ns, gc2 = gc - Ns;
                    __half2 h0 = __floats2half2_rn(ac[0], ac[1]);
                    __half2 h1 = __floats2half2_rn(ac[2], ac[3]);
                    *(__half2*)&Ch2[(size_t)gr0 * N2 + gc2] = h0;
                    *(__half2*)&Ch2[(size_t)gr1 * N2 + gc2] = h1;
                }
            }
        }
    }
}

// ---------------------------------------------------------------------------
// Flash attention (mma.sync + ldmatrix), static-offset base-2 softmax.
// Split-S retained from R10 (register-pressure relief; isolated A/B this round)
// smem: Q[128][136] | K[2][64][136] | V[2][64][136]
// ---------------------------------------------------------------------------
#define FSM_BYTES 104448
#define KVW (2 * DD)
__global__ void __launch_bounds__(256, 2) flash_h(
    const __half* __restrict__ Qg, const __half* __restrict__ KVg,
    __half* __restrict__ Og)
{
    extern __shared__ __half smh[];
    const uint32_t su = smem_to_u32(smh);
    const int tid = threadIdx.x, lane = tid & 31, wid = tid >> 5;

    // LPT decode: linear bid L -> (mtile descending in L, h, b)
    const int L = blockIdx.x + 16 * blockIdx.y + 256 * blockIdx.z;
    const int mt = 15 - (L >> 5);
    const int h = L & 15;
    const int b = (L >> 4) & 1;
    const int m0 = mt * 128;

    const int r = lane >> 2, cc = (lane & 3) * 2;
    const int laddA = lane & 15;
    const int lcolA = (lane >> 4) << 3;
    const int laddB = (lane & 7) | ((lane & 16) >> 1);
    const int lcolB = lane & 8;

    // Issue Q tile (128 rows x 256B)
#pragma unroll
    for (int u = 0; u < 8; u++) {
        int c = u * 256 + tid;
        int row = c >> 4, seg = c & 15;
        const __half* src = Qg + (size_t)(b * TT + m0 + row) * DD + h * HD + seg * 8;
        cp16(su + row * 272 + seg * 16, src);
    }
    CP_COMMIT();

    auto issueKV = [&](int it) {
        const int st = it & 1;
        const int s0 = it * 64;
        const __half* base = KVg + (size_t)(b * S_TOT + s0) * KVW + h * HD;
#pragma unroll
        for (int u = 0; u < 4; u++) {
            int c = u * 256 + tid;
            int row = c >> 4, seg = c & 15;
            cp16(su + 34816 + st * 17408 + row * 272 + seg * 16,
                 base + (size_t)row * KVW + seg * 8);
        }
#pragma unroll
        for (int u = 0; u < 4; u++) {
            int c = u * 256 + tid;
            int row = c >> 4, seg = c & 15;
            cp16(su + 69632 + st * 17408 + row * 272 + seg * 16,
                 base + (size_t)row * KVW + DD + seg * 8);
        }
    };
    issueKV(0); CP_COMMIT();

    CP_WAIT(1);
    __syncthreads();

    float oacc[16][4];
#pragma unroll
    for (int nn = 0; nn < 16; nn++)
#pragma unroll
        for (int q = 0; q < 4; q++) oacc[nn][q] = 0.f;
    float li[2] = {0.f, 0.f};
    const int trow0 = m0 + wid * 16 + r;
    const uint32_t qbase = su + ((wid * 16 + laddA) * 136 + lcolA) * 2;

    const int nchunks = 34 + 2 * mt;
    for (int it = 0; it < nchunks; it++) {
        CP_WAIT(0);
        __syncthreads();
        if (it + 1 < nchunks) issueKV(it + 1);
        CP_COMMIT();
        const int st = it & 1;
        const uint32_t ksb = su + 34816 + st * 17408;
        const uint32_t vsb = su + 69632 + st * 17408;
        const int n0s = it * 64;

#pragma unroll
        for (int jg = 0; jg < 2; jg++) {
            // S = Q K^T for 32 columns (fp32 accum); Q frags reloaded per kk
            float sacc[4][4];
#pragma unroll
            for (int j = 0; j < 4; j++)
#pragma unroll
                for (int q = 0; q < 4; q++) sacc[j][q] = 0.f;
#pragma unroll
            for (int kk = 0; kk < 8; kk++) {
                uint32_t qf[4];
                ldm_x4(qf, qbase + kk * 32);
                uint32_t kb[4][2];
#pragma unroll
                for (int jp = 0; jp < 2; jp++) {
                    uint32_t t4[4];
                    ldm_x4(t4, ksb + ((jg * 32 + 16 * jp + laddB) * 136 + kk * 16 + lcolB) * 2);
                    kb[2 * jp][0] = t4[0];   kb[2 * jp][1] = t4[1];
                    kb[2 * jp + 1][0] = t4[2]; kb[2 * jp + 1][1] = t4[3];
                }
#pragma unroll
                for (int j = 0; j < 4; j++)
                    mma16816(sacc[j], qf, kb[j]);
            }

            // p = 2^s via ex2.f16x2 (static-offset base-2 softmax)
            uint32_t pa[2][4];
#pragma unroll
            for (int hh = 0; hh < 2; hh++) {
                const int trow = trow0 + 8 * hh;
                const int vislim = PAST + trow - n0s;   // inclusive local col limit
                __half2 hs = __floats2half2_rn(0.f, 0.f);
#pragma unroll
                for (int j = 0; j < 4; j++) {
                    float v0 = sacc[j][2 * hh];
                    float v1 = sacc[j][2 * hh + 1];
                    if (vislim < 63) {
                        const int gcol = jg * 32 + 8 * j + cc;
                        if (gcol     > vislim) v0 = -1e30f;
                        if (gcol + 1 > vislim) v1 = -1e30f;
                    }
                    __half2 hl = __floats2half2_rn(v0, v1);
                    __half2 pe = h2exp2(hl);
                    pa[hh][j] = *(uint32_t*)&pe;
                    hs = __hadd2(hs, pe);
                }
                float2 fs = __half22float2(hs);
                li[hh] += fs.x + fs.y;
            }

            // O += P @ V for these 32 s-positions (V B-frags via ldmatrix.trans)
#pragma unroll
            for (int k2l = 0; k2l < 2; k2l++) {
                const int k2 = jg * 2 + k2l;
                uint32_t ap[4] = { pa[0][2 * k2l], pa[1][2 * k2l],
                                   pa[0][2 * k2l + 1], pa[1][2 * k2l + 1] };
#pragma unroll
                for (int np = 0; np < 8; np++) {
                    uint32_t t4[4];
                    ldm_x4_trans(t4, vsb + ((k2 * 16 + laddA) * 136 + np * 16 + lcolA) * 2);
                    mma16816(oacc[2 * np],     ap, &t4[0]);
                    mma16816(oacc[2 * np + 1], ap, &t4[2]);
                }
            }
        }
    }

    // Reduce li across the quad, normalize, store
#pragma unroll
    for (int hh = 0; hh < 2; hh++) {
        li[hh] += __shfl_xor_sync(0xffffffffu, li[hh], 1);
        li[hh] += __shfl_xor_sync(0xffffffffu, li[hh], 2);
    }
    const float inv0 = 1.f / li[0], inv1 = 1.f / li[1];
#pragma unroll
    for (int nn = 0; nn < 16; nn++) {
        __half2 h0 = __floats2half2_rn(oacc[nn][0] * inv0, oacc[nn][1] * inv0);
        __half2 h1 = __floats2half2_rn(oacc[nn][2] * inv1, oacc[nn][3] * inv1);
        *(__half2*)&Og[(size_t)(b * TT + trow0) * DD + h * HD + nn * 8 + cc] = h0;
        *(__half2*)&Og[(size_t)(b * TT + trow0 + 8) * DD + h * HD + nn * 8 + cc] = h1;
    }
}

// ---------------------------------------------------------------------------
extern "C" void kernel_launch(void* const* d_in, const int* in_sizes, int n_in,
                              void* d_out, int out_size)
{
    (void)in_sizes; (void)n_in; (void)out_size;
    const float* x     = (const float*)d_in[0];
    const float* lprev = (const float*)d_in[1];
    const float* Wq    = (const float*)d_in[2];
    const float* Wdown = (const float*)d_in[3];
    const float* Wk_up = (const float*)d_in[4];
    const float* Wv_up = (const float*)d_in[5];
    const float* ln_g  = (const float*)d_in[6];
    const float* ln_b  = (const float*)d_in[7];
    const float* Wo    = (const float*)d_in[8];
    float* out = (float*)d_out;

    __half *x_h, *latraw_h, *lat_h, *q_h, *kv_h, *ao_h, *WqdT, *WkvT, *WoT;
    cudaGetSymbolAddress((void**)&x_h,      g_x_h);
    cudaGetSymbolAddress((void**)&latraw_h, g_latraw_h);
    cudaGetSymbolAddress((void**)&lat_h,    g_lat_h);
    cudaGetSymbolAddress((void**)&q_h,      g_q_h);
    cudaGetSymbolAddress((void**)&kv_h,     g_kv_h);
    cudaGetSymbolAddress((void**)&ao_h,     g_ao_h);
    cudaGetSymbolAddress((void**)&WqdT,     g_WqdT);
    cudaGetSymbolAddress((void**)&WkvT,     g_WkvT);
    cudaGetSymbolAddress((void**)&WoT,      g_WoT);

    cudaFuncSetAttribute(hgemm<0>, cudaFuncAttributeMaxDynamicSharedMemorySize, 4 * GST);
    cudaFuncSetAttribute(hgemm<1>, cudaFuncAttributeMaxDynamicSharedMemorySize, 4 * GST);
    cudaFuncSetAttribute(hgemm<2>, cudaFuncAttributeMaxDynamicSharedMemorySize, 4 * GST);
    cudaFuncSetAttribute(flash_h, cudaFuncAttributeMaxDynamicSharedMemorySize, FSM_BYTES);

    // 0: fused prep (x->fp16, prev-copy, 5 transposes)
    prep_kernel<<<21504, 256>>>(x, lprev, Wq, Wdown, Wk_up, Wv_up, Wo,
                                x_h, lat_h, WqdT, WkvT, WoT);
    // 1: [q | latraw] = x @ [Wq | Wdown]  (N=2560 split epilogue)
    hgemm<2><<<dim3((DD+LAT)/128, BB*TT/128), 256, 4*GST>>>(
        x_h, WqdT, nullptr, q_h, latraw_h, BB*TT, DD+LAT, DD, DD, QSC);
    // 2: latent[:, PAST:] = LN(latraw)
    ln_kernel<<<BB*TT, 128>>>(latraw_h, ln_g, ln_b, lat_h);
    // 3: [k | v] = latent @ [Wk | Wv]  (fused KV)  [PROFILED SLOT - index 3]
    hgemm<1><<<dim3(2*DD/128, BB*S_TOT/128), 256, 4*GST>>>(
        lat_h, WkvT, nullptr, kv_h, nullptr, BB*S_TOT, 2*DD, LAT, 0, 1.f);
    // 4: flash attention -> ao
    flash_h<<<dim3(16, 16, 2), 256, FSM_BYTES>>>(q_h, kv_h, ao_h);
    // 5: out = ao @ Wo (fp32)
    hgemm<0><<<dim3(DD/128, BB*TT/128), 256, 4*GST>>>(
        ao_h, WoT, out, nullptr, nullptr, BB*TT, DD, DD, 0, 1.f);
}

// round 12
// speedup vs baseline: 1.1252x; 1.0274x over previous
#include <cuda_runtime.h>
#include <cuda_fp16.h>
#include <math.h>
#include <cstdint>

// Problem constants
#define BB 2
#define TT 2048
#define DD 2048
#define LAT 512
#define PAST 2048
#define S_TOT 4096
#define NH 16
#define HD 128
// (1/sqrt(128)) * log2(e): folded into q epilogue; softmax runs in base-2
#define QSC 0.1275164973623072f

// ---------------------------------------------------------------------------
// Scratch (device globals; no allocations allowed)
// ---------------------------------------------------------------------------
__device__ __half g_x_h[(size_t)BB*TT*DD];
__device__ __half g_latraw_h[(size_t)BB*TT*LAT];
__device__ __half g_lat_h[(size_t)BB*S_TOT*LAT];
__device__ __half g_q_h[(size_t)BB*TT*DD];
__device__ __half g_kv_h[(size_t)BB*S_TOT*2*DD];   // [s, 0:2048]=k, [s, 2048:4096]=v
__device__ __half g_ao_h[(size_t)BB*TT*DD];
__device__ __half g_WqdT[(size_t)(DD+LAT)*DD];     // rows 0..2047: WqT; 2048..2559: WdownT
__device__ __half g_WkvT[(size_t)2*DD*LAT];        // rows 0..2047: WkT; 2048..4095: WvT
__device__ __half g_WoT[(size_t)DD*DD];

// ---------------------------------------------------------------------------
// Base-target PTX helpers (sm_75/80+; no arch-'a' features)
// ---------------------------------------------------------------------------
__device__ __forceinline__ uint32_t smem_to_u32(const void* smem_ptr) {
    uint32_t addr;
    asm("{ .reg .u64 tmp; cvta.to.shared.u64 tmp, %1; cvt.u32.u64 %0, tmp; }"
        : "=r"(addr) : "l"(smem_ptr));
    return addr;
}
__device__ __forceinline__ void cp16(uint32_t dst, const void* src) {
    asm volatile("cp.async.cg.shared.global [%0], [%1], 16;" :: "r"(dst), "l"(src));
}
#define CP_COMMIT() asm volatile("cp.async.commit_group;" ::: "memory")
#define CP_WAIT(n)  asm volatile("cp.async.wait_group %0;" :: "n"(n) : "memory")

__device__ __forceinline__ void ldm_x4(uint32_t r[4], uint32_t addr) {
    asm volatile("ldmatrix.sync.aligned.m8n8.x4.shared.b16 {%0,%1,%2,%3}, [%4];"
        : "=r"(r[0]), "=r"(r[1]), "=r"(r[2]), "=r"(r[3]) : "r"(addr));
}
__device__ __forceinline__ void ldm_x4_trans(uint32_t r[4], uint32_t addr) {
    asm volatile("ldmatrix.sync.aligned.m8n8.x4.trans.shared.b16 {%0,%1,%2,%3}, [%4];"
        : "=r"(r[0]), "=r"(r[1]), "=r"(r[2]), "=r"(r[3]) : "r"(addr));
}

// m16n8k16 row.col fp16 in, fp32 accum
__device__ __forceinline__ void mma16816(float d[4], const uint32_t a[4], const uint32_t b[2]) {
    asm volatile(
        "mma.sync.aligned.m16n8k16.row.col.f32.f16.f16.f32 "
        "{%0,%1,%2,%3}, {%4,%5,%6,%7}, {%8,%9}, {%0,%1,%2,%3};"
        : "+f"(d[0]), "+f"(d[1]), "+f"(d[2]), "+f"(d[3])
        : "r"(a[0]), "r"(a[1]), "r"(a[2]), "r"(a[3]), "r"(b[0]), "r"(b[1]));
}

// ---------------------------------------------------------------------------
// Fused prep kernel: x->fp16, latent_prev copy, all 5 weight transposes.
// ---------------------------------------------------------------------------
__device__ __forceinline__ void transpose_block(
    const float* __restrict__ W, __half* __restrict__ Wt,
    int K, int N, int n0, int k0, int tid, float* t /*[32*33]*/)
{
    const int x = tid & 31, y = tid >> 5;
#pragma unroll
    for (int i = 0; i < 32; i += 8)
        t[(y + i) * 33 + x] = W[(size_t)(k0 + y + i) * N + n0 + x];
    __syncthreads();
#pragma unroll
    for (int i = 0; i < 32; i += 8)
        Wt[(size_t)(n0 + y + i) * K + k0 + x] = __float2half(t[x * 33 + y + i]);
}

__global__ void __launch_bounds__(256) prep_kernel(
    const float* __restrict__ x, const float* __restrict__ lprev,
    const float* __restrict__ Wq, const float* __restrict__ Wdown,
    const float* __restrict__ Wk, const float* __restrict__ Wv,
    const float* __restrict__ Wo,
    __half* __restrict__ x_h, __half* __restrict__ lat_h,
    __half* __restrict__ WqdT, __half* __restrict__ WkvT, __half* __restrict__ WoT)
{
    __shared__ float t[32 * 33];
    const int blk = blockIdx.x;
    const int tid = threadIdx.x;

    if (blk < 8192) {                       // x -> fp16
        size_t i = (size_t)blk * 256 + tid;
        float4 v = ((const float4*)x)[i];
        __half2* o = (__half2*)x_h + 2 * i;
        o[0] = __floats2half2_rn(v.x, v.y);
        o[1] = __floats2half2_rn(v.z, v.w);
    } else if (blk < 10240) {               // latent_prev -> fp16 into lat_h[:, :PAST]
        size_t i = (size_t)(blk - 8192) * 256 + tid;
        const size_t per_b = (size_t)PAST * LAT / 4;
        size_t b = i / per_b, r = i % per_b;
        float4 v = ((const float4*)lprev)[i];
        __half2* d = (__half2*)(lat_h + b * (size_t)S_TOT * LAT) + r * 2;
        d[0] = __floats2half2_rn(v.x, v.y);
        d[1] = __floats2half2_rn(v.z, v.w);
    } else if (blk < 14336) {               // Wq^T
        int local = blk - 10240;
        transpose_block(Wq, WqdT, DD, DD, (local & 63) * 32, (local >> 6) * 32, tid, t);
    } else if (blk < 15360) {               // Wdown^T
        int local = blk - 14336;
        transpose_block(Wdown, WqdT + (size_t)DD * DD, DD, LAT,
                        (local & 15) * 32, (local >> 4) * 32, tid, t);
    } else if (blk < 16384) {               // Wk^T
        int local = blk - 15360;
        transpose_block(Wk, WkvT, LAT, DD, (local & 63) * 32, (local >> 6) * 32, tid, t);
    } else if (blk < 17408) {               // Wv^T
        int local = blk - 16384;
        transpose_block(Wv, WkvT + (size_t)DD * LAT, LAT, DD,
                        (local & 63) * 32, (local >> 6) * 32, tid, t);
    } else {                                // Wo^T
        int local = blk - 17408;
        transpose_block(Wo, WoT, DD, DD, (local & 63) * 32, (local >> 6) * 32, tid, t);
    }
}

// ---------------------------------------------------------------------------
// LayerNorm over LAT=512 (fp16 input) -> fp16 latent
// ---------------------------------------------------------------------------
__global__ void __launch_bounds__(128) ln_kernel(
    const __half* __restrict__ raw, const float* __restrict__ g,
    const float* __restrict__ bvec, __half* __restrict__ latent)
{
    const int row = blockIdx.x;
    const int b = row / TT, t = row % TT;
    const int tid = threadIdx.x;

    const __half2* xr = (const __half2*)(raw + (size_t)row * LAT) + tid * 2;
    float2 x01 = __half22float2(xr[0]);
    float2 x23 = __half22float2(xr[1]);
    float4 xv = make_float4(x01.x, x01.y, x23.x, x23.y);
    float s = xv.x + xv.y + xv.z + xv.w;
    float s2 = xv.x * xv.x + xv.y * xv.y + xv.z * xv.z + xv.w * xv.w;

    __shared__ float red[8];
#pragma unroll
    for (int off = 16; off; off >>= 1) {
        s  += __shfl_xor_sync(0xffffffffu, s,  off);
        s2 += __shfl_xor_sync(0xffffffffu, s2, off);
    }
    const int wid = tid >> 5, lane = tid & 31;
    if (lane == 0) { red[wid] = s; red[4 + wid] = s2; }
    __syncthreads();
    s  = red[0] + red[1] + red[2] + red[3];
    s2 = red[4] + red[5] + red[6] + red[7];

    const float mean = s * (1.f / LAT);
    const float var = s2 * (1.f / LAT) - mean * mean;
    const float rs = rsqrtf(var + 1e-5f);

    float4 gv = *(const float4*)(g + tid * 4);
    float4 bv = *(const float4*)(bvec + tid * 4);
    __half2* yr = (__half2*)(latent + ((size_t)b * S_TOT + PAST + t) * LAT) + tid * 2;
    yr[0] = __floats2half2_rn((xv.x - mean) * rs * gv.x + bv.x,
                              (xv.y - mean) * rs * gv.y + bv.y);
    yr[1] = __floats2half2_rn((xv.z - mean) * rs * gv.z + bv.z,
                              (xv.w - mean) * rs * gv.w + bv.w);
}

// ---------------------------------------------------------------------------
// HGEMM (mma.sync + ldmatrix): C[M,N] = A[M,K] @ Bt[N,K]^T
// R9 config: 128x128 tile, 8 warps (2x4), warp tile 64x32, Ktile=32,
// 4-stage cp.async, __launch_bounds__(256, 2).
// EPI 0: fp32 out. EPI 1: fp16 out (scaled). EPI 2: split output.
// ---------------------------------------------------------------------------
#define GST 20480
template<int EPI>
__global__ void __launch_bounds__(256, 2) hgemm(
    const __half* __restrict__ A, const __half* __restrict__ Bt,
    float* __restrict__ Cf, __half* __restrict__ Ch, __half* __restrict__ Ch2,
    int M, int N, int K, int Ns, float oscale)
{
    extern __shared__ __half smh[];
    const uint32_t su = smem_to_u32(smh);
    const int tid = threadIdx.x;
    const int lane = tid & 31, wid = tid >> 5;
    const int wm = wid >> 2, wn = wid & 3;
    const int m0 = blockIdx.y * 128, n0 = blockIdx.x * 128;
    const int r = lane >> 2, cc = (lane & 3) * 2;
    const int laddA = lane & 15;
    const int lcolA = (lane >> 4) << 3;
    const int laddB = (lane & 7) | ((lane & 16) >> 1);
    const int lcolB = lane & 8;

    const int lrow = tid >> 1, sb2 = (tid & 1) * 2;
    const __half* Abase = A + (size_t)(m0 + lrow) * K + sb2 * 8;
    const __half* Bbase = Bt + (size_t)(n0 + lrow) * K + sb2 * 8;
    const uint32_t dA = su + lrow * 80 + sb2 * 16;
    const uint32_t dB = dA + 10240;

    float acc[4][4][4];
#pragma unroll
    for (int i = 0; i < 4; i++)
#pragma unroll
        for (int j = 0; j < 4; j++)
#pragma unroll
            for (int q = 0; q < 4; q++) acc[i][j][q] = 0.f;

    const int niter = K >> 5;
    auto issue = [&](int kt) {
        const int st = kt & 3;
        const __half* ga = Abase + kt * 32;
        const __half* gb = Bbase + kt * 32;
        cp16(dA + st * GST, ga);       cp16(dA + st * GST + 16, ga + 8);
        cp16(dB + st * GST, gb);       cp16(dB + st * GST + 16, gb + 8);
    };
    issue(0); CP_COMMIT();
    issue(1); CP_COMMIT();
    issue(2); CP_COMMIT();

    for (int kt = 0; kt < niter; kt++) {
        CP_WAIT(2);
        __syncthreads();
        if (kt + 3 < niter) issue(kt + 3);
        CP_COMMIT();
        const int st = kt & 3;
        const uint32_t asu = su + st * GST;
        const uint32_t bsu = asu + 10240;
#pragma unroll
        for (int k0 = 0; k0 < 32; k0 += 16) {
            uint32_t a[4][4], b[4][2];
#pragma unroll
            for (int i = 0; i < 4; i++)
                ldm_x4(a[i], asu + ((wm * 64 + 16 * i + laddA) * 40 + k0 + lcolA) * 2);
#pragma unroll
            for (int jp = 0; jp < 2; jp++) {
                uint32_t t4[4];
                ldm_x4(t4, bsu + ((wn * 32 + 16 * jp + laddB) * 40 + k0 + lcolB) * 2);
                b[2 * jp][0] = t4[0];   b[2 * jp][1] = t4[1];
                b[2 * jp + 1][0] = t4[2]; b[2 * jp + 1][1] = t4[3];
            }
#pragma unroll
            for (int i = 0; i < 4; i++)
#pragma unroll
                for (int j = 0; j < 4; j++)
                    mma16816(acc[i][j], a[i], b[j]);
        }
    }

#pragma unroll
    for (int i = 0; i < 4; i++) {
        const int gr0 = m0 + wm * 64 + 16 * i + r;
        const int gr1 = gr0 + 8;
#pragma unroll
        for (int j = 0; j < 4; j++) {
            const int gc = n0 + wn * 32 + 8 * j + cc;
            const float* ac = acc[i][j];
            if (EPI == 0) {
                *(float2*)&Cf[(size_t)gr0 * N + gc] = make_float2(ac[0], ac[1]);
                *(float2*)&Cf[(size_t)gr1 * N + gc] = make_float2(ac[2], ac[3]);
            } else if (EPI == 1) {
                __half2 h0 = __floats2half2_rn(ac[0] * oscale, ac[1] * oscale);
                __half2 h1 = __floats2half2_rn(ac[2] * oscale, ac[3] * oscale);
                *(__half2*)&Ch[(size_t)gr0 * N + gc] = h0;
                *(__half2*)&Ch[(size_t)gr1 * N + gc] = h1;
            } else {  // EPI == 2: split output (uniform branch per CTA)
                if (n0 < Ns) {
                    __half2 h0 = __floats2half2_rn(ac[0] * oscale, ac[1] * oscale);
                    __half2 h1 = __floats2half2_rn(ac[2] * oscale, ac[3] * oscale);
                    *(__half2*)&Ch[(size_t)gr0 * Ns + gc] = h0;
                    *(__half2*)&Ch[(size_t)gr1 * Ns + gc] = h1;
                } else {
                    const int N2 = N - Ns, gc2 = gc - Ns;
                    __half2 h0 = __floats2half2_rn(ac[0], ac[1]);
                    __half2 h1 = __floats2half2_rn(ac[2], ac[3]);
                    *(__half2*)&Ch2[(size_t)gr0 * N2 + gc2] = h0;
                    *(__half2*)&Ch2[(size_t)gr1 * N2 + gc2] = h1;
                }
            }
        }
    }
}

// ---------------------------------------------------------------------------
// HGEMM_BIG: 256x128 CTA tile, 512 threads (16 warps, 4x4), warp tile 64x32.
// Same Ktile=32 / 4-stage pipeline. Tests the L2-BW-co-limit hypothesis:
// per-kt loads 24 KB for 1M MAC (vs 2x[16 KB for 0.5M]) -> 1.33x less L2
// traffic per MAC. smem 4 x 30720 = 120 KB, 1 CTA/SM (16 warps, RF-full).
// EPI=1 only (fp16 scaled out).
// ---------------------------------------------------------------------------
#define BGAB 20480                    // A bytes per stage (256 rows x 80 B)
#define BGST 30720                    // stage bytes (A 20480 + B 10240)
__global__ void __launch_bounds__(512, 1) hgemm_big(
    const __half* __restrict__ A, const __half* __restrict__ Bt,
    __half* __restrict__ Ch, int M, int N, int K, float oscale)
{
    extern __shared__ __half smh[];
    const uint32_t su = smem_to_u32(smh);
    const int tid = threadIdx.x;
    const int lane = tid & 31, wid = tid >> 5;
    const int wm = wid >> 2, wn = wid & 3;           // 4x4 warp grid
    const int m0 = blockIdx.y * 256, n0 = blockIdx.x * 128;
    const int r = lane >> 2, cc = (lane & 3) * 2;
    const int laddA = lane & 15;
    const int lcolA = (lane >> 4) << 3;
    const int laddB = (lane & 7) | ((lane & 16) >> 1);
    const int lcolB = lane & 8;

    // Loads: A 256 rows x 64B (2 thr/row, 2 cp16 each); B 128 rows x 64B (4 thr/row, 1 cp16)
    const int arow = tid >> 1, acol = (tid & 1) * 16;   // halves
    const int brow = tid >> 2, bcol = (tid & 3) * 8;    // halves
    const __half* Abase = A + (size_t)(m0 + arow) * K + acol;
    const __half* Bbase = Bt + (size_t)(n0 + brow) * K + bcol;
    const uint32_t dA = su + arow * 80 + acol * 2;
    const uint32_t dB = su + BGAB + brow * 80 + bcol * 2;

    float acc[4][4][4];
#pragma unroll
    for (int i = 0; i < 4; i++)
#pragma unroll
        for (int j = 0; j < 4; j++)
#pragma unroll
            for (int q = 0; q < 4; q++) acc[i][j][q] = 0.f;

    const int niter = K >> 5;
    auto issue = [&](int kt) {
        const int st = kt & 3;
        const __half* ga = Abase + kt * 32;
        cp16(dA + st * BGST, ga);
        cp16(dA + st * BGST + 16, ga + 8);
        cp16(dB + st * BGST, Bbase + kt * 32);
    };
    issue(0); CP_COMMIT();
    issue(1); CP_COMMIT();
    issue(2); CP_COMMIT();

    for (int kt = 0; kt < niter; kt++) {
        CP_WAIT(2);
        __syncthreads();
        if (kt + 3 < niter) issue(kt + 3);
        CP_COMMIT();
        const int st = kt & 3;
        const uint32_t asu = su + st * BGST;
        const uint32_t bsu = asu + BGAB;
#pragma unroll
        for (int k0 = 0; k0 < 32; k0 += 16) {
            uint32_t a[4][4], b[4][2];
#pragma unroll
            for (int i = 0; i < 4; i++)
                ldm_x4(a[i], asu + ((wm * 64 + 16 * i + laddA) * 40 + k0 + lcolA) * 2);
#pragma unroll
            for (int jp = 0; jp < 2; jp++) {
                uint32_t t4[4];
                ldm_x4(t4, bsu + ((wn * 32 + 16 * jp + laddB) * 40 + k0 + lcolB) * 2);
                b[2 * jp][0] = t4[0];   b[2 * jp][1] = t4[1];
                b[2 * jp + 1][0] = t4[2]; b[2 * jp + 1][1] = t4[3];
            }
#pragma unroll
            for (int i = 0; i < 4; i++)
#pragma unroll
                for (int j = 0; j < 4; j++)
                    mma16816(acc[i][j], a[i], b[j]);
        }
    }

#pragma unroll
    for (int i = 0; i < 4; i++) {
        const int gr0 = m0 + wm * 64 + 16 * i + r;
        const int gr1 = gr0 + 8;
#pragma unroll
        for (int j = 0; j < 4; j++) {
            const int gc = n0 + wn * 32 + 8 * j + cc;
            const float* ac = acc[i][j];
            __half2 h0 = __floats2half2_rn(ac[0] * oscale, ac[1] * oscale);
            __half2 h1 = __floats2half2_rn(ac[2] * oscale, ac[3] * oscale);
            *(__half2*)&Ch[(size_t)gr0 * N + gc] = h0;
            *(__half2*)&Ch[(size_t)gr1 * N + gc] = h1;
        }
    }
}

// ---------------------------------------------------------------------------
// Flash attention (mma.sync + ldmatrix), static-offset base-2 softmax.
// R9 version restored (split-S cost +18 us: double Q-fragment loads).
// Q fragments reloaded from smem per chunk; 2 CTAs/SM.
// smem: Q[128][136] | K[2][64][136] | V[2][64][136]
// ---------------------------------------------------------------------------
#define FSM_BYTES 104448
#define KVW (2 * DD)
__global__ void __launch_bounds__(256, 2) flash_h(
    const __half* __restrict__ Qg, const __half* __restrict__ KVg,
    __half* __restrict__ Og)
{
    extern __shared__ __half smh[];
    const uint32_t su = smem_to_u32(smh);
    const int tid = threadIdx.x, lane = tid & 31, wid = tid >> 5;

    // LPT decode: linear bid L -> (mtile descending in L, h, b)
    const int L = blockIdx.x + 16 * blockIdx.y + 256 * blockIdx.z;
    const int mt = 15 - (L >> 5);
    const int h = L & 15;
    const int b = (L >> 4) & 1;
    const int m0 = mt * 128;

    const int r = lane >> 2, cc = (lane & 3) * 2;
    const int laddA = lane & 15;
    const int lcolA = (lane >> 4) << 3;
    const int laddB = (lane & 7) | ((lane & 16) >> 1);
    const int lcolB = lane & 8;

    // Issue Q tile (128 rows x 256B)
#pragma unroll
    for (int u = 0; u < 8; u++) {
        int c = u * 256 + tid;
        int row = c >> 4, seg = c & 15;
        const __half* src = Qg + (size_t)(b * TT + m0 + row) * DD + h * HD + seg * 8;
        cp16(su + row * 272 + seg * 16, src);
    }
    CP_COMMIT();

    auto issueKV = [&](int it) {
        const int st = it & 1;
        const int s0 = it * 64;
        const __half* base = KVg + (size_t)(b * S_TOT + s0) * KVW + h * HD;
#pragma unroll
        for (int u = 0; u < 4; u++) {
            int c = u * 256 + tid;
            int row = c >> 4, seg = c & 15;
            cp16(su + 34816 + st * 17408 + row * 272 + seg * 16,
                 base + (size_t)row * KVW + seg * 8);
        }
#pragma unroll
        for (int u = 0; u < 4; u++) {
            int c = u * 256 + tid;
            int row = c >> 4, seg = c & 15;
            cp16(su + 69632 + st * 17408 + row * 272 + seg * 16,
                 base + (size_t)row * KVW + DD + seg * 8);
        }
    };
    issueKV(0); CP_COMMIT();

    CP_WAIT(1);
    __syncthreads();

    float oacc[16][4];
#pragma unroll
    for (int nn = 0; nn < 16; nn++)
#pragma unroll
        for (int q = 0; q < 4; q++) oacc[nn][q] = 0.f;
    float li[2] = {0.f, 0.f};
    const int trow0 = m0 + wid * 16 + r;
    const uint32_t qbase = su + ((wid * 16 + laddA) * 136 + lcolA) * 2;

    const int nchunks = 34 + 2 * mt;
    for (int it = 0; it < nchunks; it++) {
        CP_WAIT(0);
        __syncthreads();
        if (it + 1 < nchunks) issueKV(it + 1);
        CP_COMMIT();
        const int st = it & 1;
        const uint32_t ksb = su + 34816 + st * 17408;
        const uint32_t vsb = su + 69632 + st * 17408;

        // S = Q K^T (fp32 accum); Q fragments reloaded from smem per kk
        float sacc[8][4];
#pragma unroll
        for (int j = 0; j < 8; j++)
#pragma unroll
            for (int q = 0; q < 4; q++) sacc[j][q] = 0.f;
#pragma unroll
        for (int kk = 0; kk < 8; kk++) {
            uint32_t qf[4];
            ldm_x4(qf, qbase + kk * 32);
            uint32_t kb[8][2];
#pragma unroll
            for (int jp = 0; jp < 4; jp++) {
                uint32_t t4[4];
                ldm_x4(t4, ksb + ((16 * jp + laddB) * 136 + kk * 16 + lcolB) * 2);
                kb[2 * jp][0] = t4[0];   kb[2 * jp][1] = t4[1];
                kb[2 * jp + 1][0] = t4[2]; kb[2 * jp + 1][1] = t4[3];
            }
#pragma unroll
            for (int j = 0; j < 8; j++)
                mma16816(sacc[j], qf, kb[j]);
        }

        // p = 2^s via ex2.f16x2 (exact-equivalent softmax; offset cancels)
        const int n0s = it * 64;
        uint32_t pa[2][8];
#pragma unroll
        for (int hh = 0; hh < 2; hh++) {
            const int trow = trow0 + 8 * hh;
            const int vislim = PAST + trow - n0s;
            __half2 hs = __floats2half2_rn(0.f, 0.f);
#pragma unroll
            for (int j = 0; j < 8; j++) {
                float v0 = sacc[j][2 * hh];
                float v1 = sacc[j][2 * hh + 1];
                if (vislim < 63) {
                    if (8 * j + cc     > vislim) v0 = -1e30f;
                    if (8 * j + cc + 1 > vislim) v1 = -1e30f;
                }
                __half2 hl = __floats2half2_rn(v0, v1);
                __half2 pe = h2exp2(hl);
                pa[hh][j] = *(uint32_t*)&pe;
                hs = __hadd2(hs, pe);
            }
            float2 fs = __half22float2(hs);
            li[hh] += fs.x + fs.y;
        }

        // O += P @ V  (V B-fragments via ldmatrix.trans)
#pragma unroll
        for (int k2 = 0; k2 < 4; k2++) {
            uint32_t ap[4] = { pa[0][2 * k2], pa[1][2 * k2],
                               pa[0][2 * k2 + 1], pa[1][2 * k2 + 1] };
#pragma unroll
            for (int np = 0; np < 8; np++) {
                uint32_t t4[4];
                ldm_x4_trans(t4, vsb + ((k2 * 16 + laddA) * 136 + np * 16 + lcolA) * 2);
                mma16816(oacc[2 * np],     ap, &t4[0]);
                mma16816(oacc[2 * np + 1], ap, &t4[2]);
            }
        }
    }

    // Reduce li across the quad, normalize, store
#pragma unroll
    for (int hh = 0; hh < 2; hh++) {
        li[hh] += __shfl_xor_sync(0xffffffffu, li[hh], 1);
        li[hh] += __shfl_xor_sync(0xffffffffu, li[hh], 2);
    }
    const float inv0 = 1.f / li[0], inv1 = 1.f / li[1];
#pragma unroll
    for (int nn = 0; nn < 16; nn++) {
        __half2 h0 = __floats2half2_rn(oacc[nn][0] * inv0, oacc[nn][1] * inv0);
        __half2 h1 = __floats2half2_rn(oacc[nn][2] * inv1, oacc[nn][3] * inv1);
        *(__half2*)&Og[(size_t)(b * TT + trow0) * DD + h * HD + nn * 8 + cc] = h0;
        *(__half2*)&Og[(size_t)(b * TT + trow0 + 8) * DD + h * HD + nn * 8 + cc] = h1;
    }
}

// ---------------------------------------------------------------------------
extern "C" void kernel_launch(void* const* d_in, const int* in_sizes, int n_in,
                              void* d_out, int out_size)
{
    (void)in_sizes; (void)n_in; (void)out_size;
    const float* x     = (const float*)d_in[0];
    const float* lprev = (const float*)d_in[1];
    const float* Wq    = (const float*)d_in[2];
    const float* Wdown = (const float*)d_in[3];
    const float* Wk_up = (const float*)d_in[4];
    const float* Wv_up = (const float*)d_in[5];
    const float* ln_g  = (const float*)d_in[6];
    const float* ln_b  = (const float*)d_in[7];
    const float* Wo    = (const float*)d_in[8];
    float* out = (float*)d_out;

    __half *x_h, *latraw_h, *lat_h, *q_h, *kv_h, *ao_h, *WqdT, *WkvT, *WoT;
    cudaGetSymbolAddress((void**)&x_h,      g_x_h);
    cudaGetSymbolAddress((void**)&latraw_h, g_latraw_h);
    cudaGetSymbolAddress((void**)&lat_h,    g_lat_h);
    cudaGetSymbolAddress((void**)&q_h,      g_q_h);
    cudaGetSymbolAddress((void**)&kv_h,     g_kv_h);
    cudaGetSymbolAddress((void**)&ao_h,     g_ao_h);
    cudaGetSymbolAddress((void**)&WqdT,     g_WqdT);
    cudaGetSymbolAddress((void**)&WkvT,     g_WkvT);
    cudaGetSymbolAddress((void**)&WoT,      g_WoT);

    cudaFuncSetAttribute(hgemm<0>, cudaFuncAttributeMaxDynamicSharedMemorySize, 4 * GST);
    cudaFuncSetAttribute(hgemm<2>, cudaFuncAttributeMaxDynamicSharedMemorySize, 4 * GST);
    cudaFuncSetAttribute(hgemm_big, cudaFuncAttributeMaxDynamicSharedMemorySize, 4 * BGST);
    cudaFuncSetAttribute(flash_h, cudaFuncAttributeMaxDynamicSharedMemorySize, FSM_BYTES);

    // 0: fused prep (x->fp16, prev-copy, 5 transposes)
    prep_kernel<<<21504, 256>>>(x, lprev, Wq, Wdown, Wk_up, Wv_up, Wo,
                                x_h, lat_h, WqdT, WkvT, WoT);
    // 1: [q | latraw] = x @ [Wq | Wdown]  (N=2560 split epilogue)
    hgemm<2><<<dim3((DD+LAT)/128, BB*TT/128), 256, 4*GST>>>(
        x_h, WqdT, nullptr, q_h, latraw_h, BB*TT, DD+LAT, DD, DD, QSC);
    // 2: latent[:, PAST:] = LN(latraw)
    ln_kernel<<<BB*TT, 128>>>(latraw_h, ln_g, ln_b, lat_h);
    // 3: [k | v] = latent @ [Wk | Wv]  (256x128 tile experiment) [PROFILED SLOT]
    hgemm_big<<<dim3(2*DD/128, BB*S_TOT/256), 512, 4*BGST>>>(
        lat_h, WkvT, kv_h, BB*S_TOT, 2*DD, LAT, 1.f);
    // 4: flash attention -> ao
    flash_h<<<dim3(16, 16, 2), 256, FSM_BYTES>>>(q_h, kv_h, ao_h);
    // 5: out = ao @ Wo (fp32)
    hgemm<0><<<dim3(DD/128, BB*TT/128), 256, 4*GST>>>(
        ao_h, WoT, out, nullptr, nullptr, BB*TT, DD, DD, 0, 1.f);
}